// round 5
// baseline (speedup 1.0000x reference)
#include <cuda_runtime.h>
#include <cuda_fp16.h>
#include <cstdint>

#define DIM  128
#define NMAX 100000
#define EMAX 1600000

// ---- scratch (__device__ globals: allocation-free rule) ----
__device__ __half2 g_h2[(size_t)NMAX * (DIM / 2)];  // h = x@W + b, fp16
__device__ uint2 g_edges[EMAX];                     // row-sorted (col, val_bits)
__device__ int   g_hist[NMAX];
__device__ int   g_offsets[NMAX + 1];
__device__ int   g_cursor[NMAX];
__device__ int   g_partials[1024];

// Packed fp32 FMA (SASS FFMA2 — PTX-only form)
__device__ __forceinline__ void ffma2(uint64_t& d, uint64_t a, uint64_t b) {
    asm("fma.rn.f32x2 %0, %1, %2, %0;" : "+l"(d) : "l"(a), "l"(b));
}
__device__ __forceinline__ uint64_t dup2(float v) {
    uint64_t d; asm("mov.b64 %0, {%1, %1};" : "=l"(d) : "f"(v)); return d;
}

// ---------------------------------------------------------------------------
// GEMM: h = x@W + b in fp32 (FFMA2), fp16 epilogue store.
// W row-major in smem; col-paired accumulators; x warp-broadcast + dup.
// 256 thr, 64 rows x 128 cols per block.
// ---------------------------------------------------------------------------
#define GEMM_SMEM ((DIM * DIM + 64 * DIM) * 4)   // 96 KB

__global__ void __launch_bounds__(256, 2) gemm_bias_kernel(
    const float* __restrict__ x, const float* __restrict__ W,
    const float* __restrict__ b, int n_rows)
{
    extern __shared__ float smem[];
    float* sW = smem;             // [128][128] row-major
    float* sX = smem + DIM * DIM; // [64][128] row-major

    const int tx   = threadIdx.x;
    const int row0 = blockIdx.x * 64;
    const int rows_here = min(64, n_rows - row0);

    {
        const float4* W4 = (const float4*)W;
        float4* sW4 = (float4*)sW;
        #pragma unroll
        for (int i = 0; i < 16; i++) sW4[tx + 256 * i] = W4[tx + 256 * i];
    }
    {
        const float4* X4 = (const float4*)(x + (size_t)row0 * DIM);
        float4* sX4 = (float4*)sX;
        #pragma unroll
        for (int i = 0; i < 8; i++) {
            int idx = tx + 256 * i;
            int r = idx >> 5;
            float4 v = make_float4(0.f, 0.f, 0.f, 0.f);
            if (r < rows_here) v = X4[idx];
            sX4[idx] = v;
        }
    }
    __syncthreads();

    const int cp = tx & 31;
    const int r0 = (tx >> 5) * 8;
    const uint64_t* sWp = (const uint64_t*)sW;

    uint64_t acc[8][2];
    #pragma unroll
    for (int i = 0; i < 8; i++) { acc[i][0] = 0ull; acc[i][1] = 0ull; }

    #pragma unroll 4
    for (int k = 0; k < DIM; k++) {
        uint64_t w0 = sWp[k * 64 + cp];
        uint64_t w1 = sWp[k * 64 + cp + 32];
        const float* xk = sX + k;
        #pragma unroll
        for (int i = 0; i < 8; i++) {
            uint64_t xv = dup2(xk[(r0 + i) * DIM]);
            ffma2(acc[i][0], xv, w0);
            ffma2(acc[i][1], xv, w1);
        }
    }

    float2 b0 = *(const float2*)(b + 2 * cp);
    float2 b1 = *(const float2*)(b + 2 * cp + 64);

    #pragma unroll
    for (int i = 0; i < 8; i++) {
        int r = r0 + i;
        if (r < rows_here) {
            __half2* hrow = g_h2 + (size_t)(row0 + r) * 64;
            float2 p0 = *(float2*)&acc[i][0];
            float2 p1 = *(float2*)&acc[i][1];
            p0.x += b0.x; p0.y += b0.y;
            p1.x += b1.x; p1.y += b1.y;
            // col pair (2cp,2cp+1) -> half2 slot cp; (2cp+64,2cp+65) -> cp+32
            hrow[cp]      = __float22half2_rn(p0);
            hrow[cp + 32] = __float22half2_rn(p1);
        }
    }
}

// ---------------------------------------------------------------------------
// CSR build
// ---------------------------------------------------------------------------
__global__ void __launch_bounds__(256) zero_hist_kernel(int n)
{
    int i = blockIdx.x * blockDim.x + threadIdx.x;
    if (i < n) g_hist[i] = 0;
}

__global__ void __launch_bounds__(256) hist_kernel(const int* __restrict__ rows, int n_edges)
{
    int e = blockIdx.x * blockDim.x + threadIdx.x;
    if (e < n_edges) atomicAdd(&g_hist[rows[e]], 1);
}

__device__ __forceinline__ int block_scan_incl(int v, int* wsum)
{
    int lane = threadIdx.x & 31, wid = threadIdx.x >> 5;
    int incl = v;
    #pragma unroll
    for (int o = 1; o < 32; o <<= 1) {
        int t = __shfl_up_sync(0xffffffffu, incl, o);
        if (lane >= o) incl += t;
    }
    if (lane == 31) wsum[wid] = incl;
    __syncthreads();
    if (wid == 0) {
        int w = wsum[lane];
        #pragma unroll
        for (int o = 1; o < 32; o <<= 1) {
            int t = __shfl_up_sync(0xffffffffu, w, o);
            if (lane >= o) w += t;
        }
        wsum[lane] = w;
    }
    __syncthreads();
    if (wid > 0) incl += wsum[wid - 1];
    return incl;
}

__global__ void __launch_bounds__(1024) scan_a_kernel(int n)
{
    __shared__ int wsum[32];
    int i = blockIdx.x * 1024 + threadIdx.x;
    int v = (i < n) ? g_hist[i] : 0;
    int incl = block_scan_incl(v, wsum);
    if (i < n) g_offsets[i] = incl - v;
    if (threadIdx.x == 1023) g_partials[blockIdx.x] = incl;
}

__global__ void __launch_bounds__(1024) scan_b_kernel(int nb)
{
    __shared__ int wsum[32];
    int i = threadIdx.x;
    int v = (i < nb) ? g_partials[i] : 0;
    int incl = block_scan_incl(v, wsum);
    if (i < nb) g_partials[i] = incl - v;
}

__global__ void __launch_bounds__(1024) scan_c_kernel(int n, int n_edges)
{
    int i = blockIdx.x * 1024 + threadIdx.x;
    if (i < n) {
        int o = g_offsets[i] + g_partials[blockIdx.x];
        g_offsets[i] = o;
        g_cursor[i]  = o;
    }
    if (i == 0) g_offsets[n] = n_edges;
}

__global__ void __launch_bounds__(256) permute_kernel(
    const float* __restrict__ vals, const int* __restrict__ rows,
    const int* __restrict__ cols, int n_edges)
{
    int e = blockIdx.x * blockDim.x + threadIdx.x;
    if (e >= n_edges) return;
    int r = rows[e];
    int p = atomicAdd(&g_cursor[r], 1);
    g_edges[p] = make_uint2((unsigned)cols[e], __float_as_uint(vals[e]));
}

// ---------------------------------------------------------------------------
// Aggregate: one warp per row. Lane loads uint2 = 4 fp16 cols per edge
// (coalesced 256B/edge), converts to fp32, accumulates fp32, MLP=4.
// ---------------------------------------------------------------------------
__device__ __forceinline__ void acc_edge(float4& acc, float v, uint2 hbits)
{
    float2 a = __half22float2(*(__half2*)&hbits.x);
    float2 c = __half22float2(*(__half2*)&hbits.y);
    acc.x += v * a.x; acc.y += v * a.y;
    acc.z += v * c.x; acc.w += v * c.y;
}

__global__ void __launch_bounds__(256) aggregate_kernel(
    float4* __restrict__ out, int n_nodes)
{
    int gid  = blockIdx.x * blockDim.x + threadIdx.x;
    int r    = gid >> 5;
    int lane = gid & 31;
    if (r >= n_nodes) return;

    int beg = __ldg(&g_offsets[r]);
    int end = __ldg(&g_offsets[r + 1]);

    const uint2* h2 = (const uint2*)g_h2;   // row stride 32 uint2
    float4 acc = make_float4(0.f, 0.f, 0.f, 0.f);

    int i = beg;
    for (; i + 3 < end; i += 4) {
        uint2 e0 = __ldg(&g_edges[i]);
        uint2 e1 = __ldg(&g_edges[i + 1]);
        uint2 e2 = __ldg(&g_edges[i + 2]);
        uint2 e3 = __ldg(&g_edges[i + 3]);
        uint2 h0 = __ldg(h2 + (size_t)e0.x * 32 + lane);
        uint2 h1 = __ldg(h2 + (size_t)e1.x * 32 + lane);
        uint2 h2v = __ldg(h2 + (size_t)e2.x * 32 + lane);
        uint2 h3 = __ldg(h2 + (size_t)e3.x * 32 + lane);
        acc_edge(acc, __uint_as_float(e0.y), h0);
        acc_edge(acc, __uint_as_float(e1.y), h1);
        acc_edge(acc, __uint_as_float(e2.y), h2v);
        acc_edge(acc, __uint_as_float(e3.y), h3);
    }
    for (; i < end; i++) {
        uint2 e0 = __ldg(&g_edges[i]);
        uint2 h0 = __ldg(h2 + (size_t)e0.x * 32 + lane);
        acc_edge(acc, __uint_as_float(e0.y), h0);
    }

    // lane owns half2 slots lane*2, lane*2+1 = cols (4*lane .. 4*lane+3)... 
    // mapping check: h2 slot s holds cols (2s, 2s+1); lane loads slots 2*lane,2*lane+1
    // via uint2 at index lane -> cols 4*lane..4*lane+3. Matches out float4 at lane.
    out[(size_t)r * 32 + lane] = acc;
}

// ---------------------------------------------------------------------------
// Launch: fork/join two-branch graph; aggregate joins.
// ---------------------------------------------------------------------------
extern "C" void kernel_launch(void* const* d_in, const int* in_sizes, int n_in,
                              void* d_out, int out_size)
{
    const float* x    = (const float*)d_in[0];
    const float* W    = (const float*)d_in[1];
    const float* b    = (const float*)d_in[2];
    const float* vals = (const float*)d_in[3];
    const int*   rows = (const int*)d_in[4];
    const int*   cols = (const int*)d_in[5];
    float4*      out  = (float4*)d_out;

    const int n_nodes = in_sizes[0] / DIM;
    const int n_edges = in_sizes[3];

    static cudaStream_t sB;
    static cudaEvent_t  evFork, evJoin;
    static bool init = false;
    if (!init) {
        cudaFuncSetAttribute(gemm_bias_kernel,
                             cudaFuncAttributeMaxDynamicSharedMemorySize, GEMM_SMEM);
        cudaStreamCreateWithFlags(&sB, cudaStreamNonBlocking);
        cudaEventCreateWithFlags(&evFork, cudaEventDisableTiming);
        cudaEventCreateWithFlags(&evJoin, cudaEventDisableTiming);
        init = true;
    }

    const int nb = (n_nodes + 1023) / 1024;

    // fork
    cudaEventRecord(evFork, 0);
    cudaStreamWaitEvent(sB, evFork, 0);

    // branch B: CSR build
    zero_hist_kernel<<<(n_nodes + 255) / 256, 256, 0, sB>>>(n_nodes);
    hist_kernel<<<(n_edges + 255) / 256, 256, 0, sB>>>(rows, n_edges);
    scan_a_kernel<<<nb, 1024, 0, sB>>>(n_nodes);
    scan_b_kernel<<<1, 1024, 0, sB>>>(nb);
    scan_c_kernel<<<nb, 1024, 0, sB>>>(n_nodes, n_edges);
    permute_kernel<<<(n_edges + 255) / 256, 256, 0, sB>>>(vals, rows, cols, n_edges);

    // branch A: GEMM
    gemm_bias_kernel<<<(n_nodes + 63) / 64, 256, GEMM_SMEM>>>(x, W, b, n_nodes);

    // join
    cudaEventRecord(evJoin, sB);
    cudaStreamWaitEvent(0, evJoin, 0);

    // aggregate
    {
        long long total_threads = (long long)n_nodes * 32;
        int blocks = (int)((total_threads + 255) / 256);
        aggregate_kernel<<<blocks, 256>>>(out, n_nodes);
    }
}

// round 9
// speedup vs baseline: 1.7386x; 1.7386x over previous
#include <cuda_runtime.h>
#include <cuda_fp16.h>
#include <cstdint>

#define DIM  128
#define NMAX 100000
#define EMAX 1600000
#define LDK  136   // padded k-stride (halves) -> 272B rows, conflict-free ldmatrix

// ---- scratch (__device__ globals: allocation-free rule) ----
__device__ float  g_h[(size_t)NMAX * DIM];     // h = x@W + b (fp32)
__device__ __half g_wt16[DIM * LDK];           // W^T fp16 [n][k], padded
__device__ uint2  g_edges[EMAX];               // row-sorted (col, val_bits)
__device__ int    g_hist[NMAX];
__device__ int    g_offsets[NMAX + 1];
__device__ int    g_cursor[NMAX];
__device__ int    g_partials[1024];

// ---------------------------------------------------------------------------
// MMA helpers (sm_80-class: compile fine for compute_103)
// ---------------------------------------------------------------------------
__device__ __forceinline__ uint32_t smem_u32(const void* p) {
    uint32_t a;
    asm("{ .reg .u64 t; cvta.to.shared.u64 t, %1; cvt.u32.u64 %0, t; }"
        : "=r"(a) : "l"(p));
    return a;
}

#define LDSM4(r0, r1, r2, r3, addr)                                        \
    asm volatile("ldmatrix.sync.aligned.m8n8.x4.shared.b16 {%0,%1,%2,%3}, [%4];" \
                 : "=r"(r0), "=r"(r1), "=r"(r2), "=r"(r3) : "r"(addr))

__device__ __forceinline__ void mma16816(
    float* c, uint32_t a0, uint32_t a1, uint32_t a2, uint32_t a3,
    uint32_t b0, uint32_t b1)
{
    asm volatile(
        "mma.sync.aligned.m16n8k16.row.col.f32.f16.f16.f32 "
        "{%0,%1,%2,%3}, {%4,%5,%6,%7}, {%8,%9}, {%0,%1,%2,%3};"
        : "+f"(c[0]), "+f"(c[1]), "+f"(c[2]), "+f"(c[3])
        : "r"(a0), "r"(a1), "r"(a2), "r"(a3), "r"(b0), "r"(b1));
}

// ---------------------------------------------------------------------------
// One-shot W packer: g_wt16[n][k] = fp16(W[k][n])  (runs each replay, ~3us)
// ---------------------------------------------------------------------------
__global__ void __launch_bounds__(256) pack_w_kernel(const float* __restrict__ W)
{
    int idx = blockIdx.x * 256 + threadIdx.x;   // 16384
    if (idx < DIM * DIM) {
        int k = idx >> 7, n = idx & 127;
        g_wt16[n * LDK + k] = __float2half_rn(W[k * DIM + n]);
    }
}

// ---------------------------------------------------------------------------
// GEMM via mma.sync: h = x@W + b
//   CTA: 256 thr (8 warps), tile M=128 x N=128, K=128 (8 k-steps of 16).
//   Warp w owns rows w*16..w*16+15; 16 n-blocks of 8 cols.
//   smem: sX fp16 [128][LDK], sW fp16 [128 n][LDK], bias fp32 [128].
// ---------------------------------------------------------------------------
#define SM_W_OFF   (DIM * LDK * 2)        // 34816
#define SM_B_OFF   (2 * DIM * LDK * 2)    // 69632
#define GEMM_SMEM  (SM_B_OFF + DIM * 4)   // 70144

__global__ void __launch_bounds__(256, 2) gemm_tc_kernel(
    const float* __restrict__ x, const float* __restrict__ b, int n_rows)
{
    extern __shared__ char smem[];
    __half* sX = (__half*)smem;
    float*  sB = (float*)(smem + SM_B_OFF);

    const int tx   = threadIdx.x;
    const int wid  = tx >> 5, lane = tx & 31;
    const int row0 = blockIdx.x * 128;

    // --- A fill: fp32 x -> fp16 (cheap F2FP), padded row-major ---
    {
        const float4* X4 = (const float4*)(x + (size_t)row0 * DIM);
        #pragma unroll
        for (int i = 0; i < 16; i++) {
            int idx = tx + 256 * i;            // 4096 float4 = 128 rows x 32
            int r = idx >> 5, c4 = idx & 31;
            float4 v = make_float4(0.f, 0.f, 0.f, 0.f);
            if (row0 + r < n_rows) v = X4[idx];
            __half2 h0 = __float22half2_rn(make_float2(v.x, v.y));
            __half2 h1 = __float22half2_rn(make_float2(v.z, v.w));
            *(uint2*)(sX + r * LDK + c4 * 4) =
                make_uint2(*(uint32_t*)&h0, *(uint32_t*)&h1);
        }
    }
    // --- B fill: raw copy of pre-packed fp16 W^T (incl. padding) ---
    {
        const uint4* src = (const uint4*)g_wt16;   // 2176 uint4
        uint4* dst = (uint4*)(smem + SM_W_OFF);
        #pragma unroll
        for (int i = 0; i < 9; i++) {
            int idx = tx + 256 * i;
            if (idx < (DIM * LDK * 2) / 16) dst[idx] = src[idx];
        }
    }
    if (tx < DIM) sB[tx] = b[tx];
    __syncthreads();

    // fragment base addresses
    const uint32_t base = smem_u32(smem);
    const uint32_t sxa = base + ((wid * 16 + (lane & 15)) * LDK + (lane >> 4) * 8) * 2;
    const uint32_t swa = base + SM_W_OFF + ((lane & 15) * LDK + (lane >> 4) * 8) * 2;

    float acc[16][4];
    #pragma unroll
    for (int j = 0; j < 16; j++)
        #pragma unroll
        for (int q = 0; q < 4; q++) acc[j][q] = 0.f;

    #pragma unroll
    for (int s = 0; s < 8; s++) {
        uint32_t a0, a1, a2, a3;
        LDSM4(a0, a1, a2, a3, sxa + s * 32);           // k-step = 16 halves = 32B
        #pragma unroll
        for (int j = 0; j < 8; j++) {                  // n16 block pair
            uint32_t b0, b1, b2, b3;
            LDSM4(b0, b1, b2, b3, swa + j * (16 * LDK * 2) + s * 32);
            mma16816(acc[2 * j],     a0, a1, a2, a3, b0, b2);
            mma16816(acc[2 * j + 1], a0, a1, a2, a3, b1, b3);
        }
    }

    // --- epilogue: bias + store fp32 h ---
    {
        int rA = row0 + wid * 16 + (lane >> 2);
        int rB = rA + 8;
        int cb = (lane & 3) * 2;
        #pragma unroll
        for (int jj = 0; jj < 16; jj++) {
            int col = jj * 8 + cb;
            float2 bv = *(float2*)(sB + col);
            if (rA < n_rows) {
                float2 v = make_float2(acc[jj][0] + bv.x, acc[jj][1] + bv.y);
                *(float2*)(g_h + (size_t)rA * DIM + col) = v;
            }
            if (rB < n_rows) {
                float2 v = make_float2(acc[jj][2] + bv.x, acc[jj][3] + bv.y);
                *(float2*)(g_h + (size_t)rB * DIM + col) = v;
            }
        }
    }
}

// ---------------------------------------------------------------------------
// CSR build (round-4)
// ---------------------------------------------------------------------------
__global__ void __launch_bounds__(256) zero_hist_kernel(int n)
{
    int i = blockIdx.x * blockDim.x + threadIdx.x;
    if (i < n) g_hist[i] = 0;
}

__global__ void __launch_bounds__(256) hist_kernel(const int* __restrict__ rows, int n_edges)
{
    int e = blockIdx.x * blockDim.x + threadIdx.x;
    if (e < n_edges) atomicAdd(&g_hist[rows[e]], 1);
}

__device__ __forceinline__ int block_scan_incl(int v, int* wsum)
{
    int lane = threadIdx.x & 31, wid = threadIdx.x >> 5;
    int incl = v;
    #pragma unroll
    for (int o = 1; o < 32; o <<= 1) {
        int t = __shfl_up_sync(0xffffffffu, incl, o);
        if (lane >= o) incl += t;
    }
    if (lane == 31) wsum[wid] = incl;
    __syncthreads();
    if (wid == 0) {
        int w = wsum[lane];
        #pragma unroll
        for (int o = 1; o < 32; o <<= 1) {
            int t = __shfl_up_sync(0xffffffffu, w, o);
            if (lane >= o) w += t;
        }
        wsum[lane] = w;
    }
    __syncthreads();
    if (wid > 0) incl += wsum[wid - 1];
    return incl;
}

__global__ void __launch_bounds__(1024) scan_a_kernel(int n)
{
    __shared__ int wsum[32];
    int i = blockIdx.x * 1024 + threadIdx.x;
    int v = (i < n) ? g_hist[i] : 0;
    int incl = block_scan_incl(v, wsum);
    if (i < n) g_offsets[i] = incl - v;
    if (threadIdx.x == 1023) g_partials[blockIdx.x] = incl;
}

__global__ void __launch_bounds__(1024) scan_b_kernel(int nb)
{
    __shared__ int wsum[32];
    int i = threadIdx.x;
    int v = (i < nb) ? g_partials[i] : 0;
    int incl = block_scan_incl(v, wsum);
    if (i < nb) g_partials[i] = incl - v;
}

__global__ void __launch_bounds__(1024) scan_c_kernel(int n, int n_edges)
{
    int i = blockIdx.x * 1024 + threadIdx.x;
    if (i < n) {
        int o = g_offsets[i] + g_partials[blockIdx.x];
        g_offsets[i] = o;
        g_cursor[i]  = o;
    }
    if (i == 0) g_offsets[n] = n_edges;
}

__global__ void __launch_bounds__(256) permute_kernel(
    const float* __restrict__ vals, const int* __restrict__ rows,
    const int* __restrict__ cols, int n_edges)
{
    int e = blockIdx.x * blockDim.x + threadIdx.x;
    if (e >= n_edges) return;
    int r = rows[e];
    int p = atomicAdd(&g_cursor[r], 1);
    g_edges[p] = make_uint2((unsigned)cols[e], __float_as_uint(vals[e]));
}

// ---------------------------------------------------------------------------
// Aggregate: one warp per row, fp32, MLP=4, atomic-free.
// ---------------------------------------------------------------------------
__global__ void __launch_bounds__(256) aggregate_kernel(
    float4* __restrict__ out, int n_nodes)
{
    int gid  = blockIdx.x * blockDim.x + threadIdx.x;
    int r    = gid >> 5;
    int lane = gid & 31;
    if (r >= n_nodes) return;

    int beg = __ldg(&g_offsets[r]);
    int end = __ldg(&g_offsets[r + 1]);

    const float4* h4 = (const float4*)g_h;
    float4 acc = make_float4(0.f, 0.f, 0.f, 0.f);

    int i = beg;
    for (; i + 3 < end; i += 4) {
        uint2 e0 = __ldg(&g_edges[i]);
        uint2 e1 = __ldg(&g_edges[i + 1]);
        uint2 e2 = __ldg(&g_edges[i + 2]);
        uint2 e3 = __ldg(&g_edges[i + 3]);
        float4 h0 = __ldg(h4 + (size_t)e0.x * 32 + lane);
        float4 h1 = __ldg(h4 + (size_t)e1.x * 32 + lane);
        float4 h2 = __ldg(h4 + (size_t)e2.x * 32 + lane);
        float4 h3 = __ldg(h4 + (size_t)e3.x * 32 + lane);
        float v0 = __uint_as_float(e0.y);
        float v1 = __uint_as_float(e1.y);
        float v2 = __uint_as_float(e2.y);
        float v3 = __uint_as_float(e3.y);
        acc.x += v0 * h0.x + v1 * h1.x + v2 * h2.x + v3 * h3.x;
        acc.y += v0 * h0.y + v1 * h1.y + v2 * h2.y + v3 * h3.y;
        acc.z += v0 * h0.z + v1 * h1.z + v2 * h2.z + v3 * h3.z;
        acc.w += v0 * h0.w + v1 * h1.w + v2 * h2.w + v3 * h3.w;
    }
    for (; i < end; i++) {
        uint2 e0 = __ldg(&g_edges[i]);
        float4 h0 = __ldg(h4 + (size_t)e0.x * 32 + lane);
        float v0 = __uint_as_float(e0.y);
        acc.x += v0 * h0.x; acc.y += v0 * h0.y;
        acc.z += v0 * h0.z; acc.w += v0 * h0.w;
    }

    out[(size_t)r * 32 + lane] = acc;
}

// ---------------------------------------------------------------------------
// Launch: fork/join two-branch graph; aggregate joins.
// ---------------------------------------------------------------------------
extern "C" void kernel_launch(void* const* d_in, const int* in_sizes, int n_in,
                              void* d_out, int out_size)
{
    const float* x    = (const float*)d_in[0];
    const float* W    = (const float*)d_in[1];
    const float* b    = (const float*)d_in[2];
    const float* vals = (const float*)d_in[3];
    const int*   rows = (const int*)d_in[4];
    const int*   cols = (const int*)d_in[5];
    float4*      out  = (float4*)d_out;

    const int n_nodes = in_sizes[0] / DIM;
    const int n_edges = in_sizes[3];

    static cudaStream_t sB;
    static cudaEvent_t  evFork, evJoin;
    static bool init = false;
    if (!init) {
        cudaFuncSetAttribute(gemm_tc_kernel,
                             cudaFuncAttributeMaxDynamicSharedMemorySize, GEMM_SMEM);
        cudaStreamCreateWithFlags(&sB, cudaStreamNonBlocking);
        cudaEventCreateWithFlags(&evFork, cudaEventDisableTiming);
        cudaEventCreateWithFlags(&evJoin, cudaEventDisableTiming);
        init = true;
    }

    const int nb = (n_nodes + 1023) / 1024;

    // fork
    cudaEventRecord(evFork, 0);
    cudaStreamWaitEvent(sB, evFork, 0);

    // branch B: CSR build
    zero_hist_kernel<<<(n_nodes + 255) / 256, 256, 0, sB>>>(n_nodes);
    hist_kernel<<<(n_edges + 255) / 256, 256, 0, sB>>>(rows, n_edges);
    scan_a_kernel<<<nb, 1024, 0, sB>>>(n_nodes);
    scan_b_kernel<<<1, 1024, 0, sB>>>(nb);
    scan_c_kernel<<<nb, 1024, 0, sB>>>(n_nodes, n_edges);
    permute_kernel<<<(n_edges + 255) / 256, 256, 0, sB>>>(vals, rows, cols, n_edges);

    // branch A: pack W (fp16) then HMMA GEMM
    pack_w_kernel<<<(DIM * DIM + 255) / 256, 256>>>(W);
    gemm_tc_kernel<<<(n_nodes + 127) / 128, 256, GEMM_SMEM>>>(x, b, n_nodes);

    // join
    cudaEventRecord(evJoin, sB);
    cudaStreamWaitEvent(0, evJoin, 0);

    // aggregate
    {
        long long total_threads = (long long)n_nodes * 32;
        int blocks = (int)((total_threads + 255) / 256);
        aggregate_kernel<<<blocks, 256>>>(out, n_nodes);
    }
}

// round 11
// speedup vs baseline: 1.8929x; 1.0888x over previous
#include <cuda_runtime.h>
#include <cuda_fp16.h>
#include <cstdint>

#define DIM  128
#define NMAX 100000
#define EMAX 1600000
#define LDK  136   // padded k-stride (halves) -> 272B rows, conflict-free ldmatrix

// ---- scratch (__device__ globals: allocation-free rule) ----
__device__ __half g_h16[(size_t)NMAX * DIM];   // h = x@W + b (fp16, 25.6MB)
__device__ __half g_wt16[DIM * LDK];           // W^T fp16 [n][k], padded
__device__ uint2  g_edges[EMAX];               // row-sorted (col, half2(v,v) bits)
__device__ int    g_hist[NMAX];
__device__ int    g_offsets[NMAX + 1];
__device__ int    g_cursor[NMAX];
__device__ int    g_partials[1024];

// ---------------------------------------------------------------------------
// MMA helpers (sm_80-class: compile fine for compute_103)
// ---------------------------------------------------------------------------
__device__ __forceinline__ uint32_t smem_u32(const void* p) {
    uint32_t a;
    asm("{ .reg .u64 t; cvta.to.shared.u64 t, %1; cvt.u32.u64 %0, t; }"
        : "=r"(a) : "l"(p));
    return a;
}

#define LDSM4(r0, r1, r2, r3, addr)                                        \
    asm volatile("ldmatrix.sync.aligned.m8n8.x4.shared.b16 {%0,%1,%2,%3}, [%4];" \
                 : "=r"(r0), "=r"(r1), "=r"(r2), "=r"(r3) : "r"(addr))

__device__ __forceinline__ void mma16816(
    float* c, uint32_t a0, uint32_t a1, uint32_t a2, uint32_t a3,
    uint32_t b0, uint32_t b1)
{
    asm volatile(
        "mma.sync.aligned.m16n8k16.row.col.f32.f16.f16.f32 "
        "{%0,%1,%2,%3}, {%4,%5,%6,%7}, {%8,%9}, {%0,%1,%2,%3};"
        : "+f"(c[0]), "+f"(c[1]), "+f"(c[2]), "+f"(c[3])
        : "r"(a0), "r"(a1), "r"(a2), "r"(a3), "r"(b0), "r"(b1));
}

// ---------------------------------------------------------------------------
// W packer: g_wt16[n][k] = fp16(W[k][n])  (runs each replay, ~3us)
// ---------------------------------------------------------------------------
__global__ void __launch_bounds__(256) pack_w_kernel(const float* __restrict__ W)
{
    int idx = blockIdx.x * 256 + threadIdx.x;   // 16384
    if (idx < DIM * DIM) {
        int k = idx >> 7, n = idx & 127;
        g_wt16[n * LDK + k] = __float2half_rn(W[k * DIM + n]);
    }
}

// ---------------------------------------------------------------------------
// GEMM via mma.sync: h = x@W + b, fp16 h output (packed F2FP epilogue).
//   CTA: 256 thr (8 warps), tile M=128 x N=128, K=128 (8 k-steps of 16).
// ---------------------------------------------------------------------------
#define SM_W_OFF   (DIM * LDK * 2)        // 34816
#define SM_B_OFF   (2 * DIM * LDK * 2)    // 69632
#define GEMM_SMEM  (SM_B_OFF + DIM * 4)   // 70144

__global__ void __launch_bounds__(256, 2) gemm_tc_kernel(
    const float* __restrict__ x, const float* __restrict__ b, int n_rows)
{
    extern __shared__ char smem[];
    __half* sX = (__half*)smem;
    float*  sB = (float*)(smem + SM_B_OFF);

    const int tx   = threadIdx.x;
    const int wid  = tx >> 5, lane = tx & 31;
    const int row0 = blockIdx.x * 128;

    // --- A fill: fp32 x -> fp16 (cheap packed F2FP), padded row-major ---
    {
        const float4* X4 = (const float4*)(x + (size_t)row0 * DIM);
        #pragma unroll
        for (int i = 0; i < 16; i++) {
            int idx = tx + 256 * i;            // 4096 float4 = 128 rows x 32
            int r = idx >> 5, c4 = idx & 31;
            float4 v = make_float4(0.f, 0.f, 0.f, 0.f);
            if (row0 + r < n_rows) v = X4[idx];
            __half2 h0 = __float22half2_rn(make_float2(v.x, v.y));
            __half2 h1 = __float22half2_rn(make_float2(v.z, v.w));
            *(uint2*)(sX + r * LDK + c4 * 4) =
                make_uint2(*(uint32_t*)&h0, *(uint32_t*)&h1);
        }
    }
    // --- B fill: raw copy of pre-packed fp16 W^T (incl. padding) ---
    {
        const uint4* src = (const uint4*)g_wt16;   // 2176 uint4
        uint4* dst = (uint4*)(smem + SM_W_OFF);
        #pragma unroll
        for (int i = 0; i < 9; i++) {
            int idx = tx + 256 * i;
            if (idx < (DIM * LDK * 2) / 16) dst[idx] = src[idx];
        }
    }
    if (tx < DIM) sB[tx] = b[tx];
    __syncthreads();

    // fragment base addresses
    const uint32_t base = smem_u32(smem);
    const uint32_t sxa = base + ((wid * 16 + (lane & 15)) * LDK + (lane >> 4) * 8) * 2;
    const uint32_t swa = base + SM_W_OFF + ((lane & 15) * LDK + (lane >> 4) * 8) * 2;

    float acc[16][4];
    #pragma unroll
    for (int j = 0; j < 16; j++)
        #pragma unroll
        for (int q = 0; q < 4; q++) acc[j][q] = 0.f;

    #pragma unroll
    for (int s = 0; s < 8; s++) {
        uint32_t a0, a1, a2, a3;
        LDSM4(a0, a1, a2, a3, sxa + s * 32);           // k-step = 16 halves = 32B
        #pragma unroll
        for (int j = 0; j < 8; j++) {                  // n16 block pair
            uint32_t b0, b1, b2, b3;
            LDSM4(b0, b1, b2, b3, swa + j * (16 * LDK * 2) + s * 32);
            mma16816(acc[2 * j],     a0, a1, a2, a3, b0, b2);
            mma16816(acc[2 * j + 1], a0, a1, a2, a3, b1, b3);
        }
    }

    // --- epilogue: bias + packed fp32->fp16 store ---
    {
        int rA = row0 + wid * 16 + (lane >> 2);
        int rB = rA + 8;
        int cb = (lane & 3) * 2;
        #pragma unroll
        for (int jj = 0; jj < 16; jj++) {
            int col = jj * 8 + cb;
            float2 bv = *(float2*)(sB + col);
            if (rA < n_rows) {
                __half2 hv = __float22half2_rn(
                    make_float2(acc[jj][0] + bv.x, acc[jj][1] + bv.y));
                *(__half2*)(g_h16 + (size_t)rA * DIM + col) = hv;
            }
            if (rB < n_rows) {
                __half2 hv = __float22half2_rn(
                    make_float2(acc[jj][2] + bv.x, acc[jj][3] + bv.y));
                *(__half2*)(g_h16 + (size_t)rB * DIM + col) = hv;
            }
        }
    }
}

// ---------------------------------------------------------------------------
// CSR build
// ---------------------------------------------------------------------------
__global__ void __launch_bounds__(256) zero_hist_kernel(int n)
{
    int i = blockIdx.x * blockDim.x + threadIdx.x;
    if (i < n) g_hist[i] = 0;
}

__global__ void __launch_bounds__(256) hist_kernel(const int* __restrict__ rows, int n_edges)
{
    int e = blockIdx.x * blockDim.x + threadIdx.x;
    if (e < n_edges) atomicAdd(&g_hist[rows[e]], 1);
}

__device__ __forceinline__ int block_scan_incl(int v, int* wsum)
{
    int lane = threadIdx.x & 31, wid = threadIdx.x >> 5;
    int incl = v;
    #pragma unroll
    for (int o = 1; o < 32; o <<= 1) {
        int t = __shfl_up_sync(0xffffffffu, incl, o);
        if (lane >= o) incl += t;
    }
    if (lane == 31) wsum[wid] = incl;
    __syncthreads();
    if (wid == 0) {
        int w = wsum[lane];
        #pragma unroll
        for (int o = 1; o < 32; o <<= 1) {
            int t = __shfl_up_sync(0xffffffffu, w, o);
            if (lane >= o) w += t;
        }
        wsum[lane] = w;
    }
    __syncthreads();
    if (wid > 0) incl += wsum[wid - 1];
    return incl;
}

__global__ void __launch_bounds__(1024) scan_a_kernel(int n)
{
    __shared__ int wsum[32];
    int i = blockIdx.x * 1024 + threadIdx.x;
    int v = (i < n) ? g_hist[i] : 0;
    int incl = block_scan_incl(v, wsum);
    if (i < n) g_offsets[i] = incl - v;
    if (threadIdx.x == 1023) g_partials[blockIdx.x] = incl;
}

__global__ void __launch_bounds__(1024) scan_b_kernel(int nb)
{
    __shared__ int wsum[32];
    int i = threadIdx.x;
    int v = (i < nb) ? g_partials[i] : 0;
    int incl = block_scan_incl(v, wsum);
    if (i < nb) g_partials[i] = incl - v;
}

__global__ void __launch_bounds__(1024) scan_c_kernel(int n, int n_edges)
{
    int i = blockIdx.x * 1024 + threadIdx.x;
    if (i < n) {
        int o = g_offsets[i] + g_partials[blockIdx.x];
        g_offsets[i] = o;
        g_cursor[i]  = o;
    }
    if (i == 0) g_offsets[n] = n_edges;
}

// permute: converts val to packed half2(v,v) ONCE so the aggregate never
// touches the scalar F2F pipe for vals.
__global__ void __launch_bounds__(256) permute_kernel(
    const float* __restrict__ vals, const int* __restrict__ rows,
    const int* __restrict__ cols, int n_edges)
{
    int e = blockIdx.x * blockDim.x + threadIdx.x;
    if (e >= n_edges) return;
    int r = rows[e];
    int p = atomicAdd(&g_cursor[r], 1);
    __half2 hv = __float2half2_rn(vals[e]);
    g_edges[p] = make_uint2((unsigned)cols[e], *(uint32_t*)&hv);
}

// ---------------------------------------------------------------------------
// Aggregate: one warp per row. fp16 gather (uint2 = 4 cols/lane, 256B/edge),
// HFMA2 accumulate in fp16 over 4-edge groups, flush each group to fp32.
// Conversions: 4 F2F per 4 edges per lane (1/edge) — hidden under memory.
// ---------------------------------------------------------------------------
__global__ void __launch_bounds__(256) aggregate_kernel(
    float4* __restrict__ out, int n_nodes)
{
    int gid  = blockIdx.x * blockDim.x + threadIdx.x;
    int r    = gid >> 5;
    int lane = gid & 31;
    if (r >= n_nodes) return;

    int beg = __ldg(&g_offsets[r]);
    int end = __ldg(&g_offsets[r + 1]);

    const uint2* h2 = (const uint2*)g_h16;   // row stride = 32 uint2 (256B)
    float4 acc = make_float4(0.f, 0.f, 0.f, 0.f);

    int i = beg;
    for (; i + 3 < end; i += 4) {
        uint2 e0 = __ldg(&g_edges[i]);
        uint2 e1 = __ldg(&g_edges[i + 1]);
        uint2 e2 = __ldg(&g_edges[i + 2]);
        uint2 e3 = __ldg(&g_edges[i + 3]);
        uint2 h0 = __ldg(h2 + (size_t)e0.x * 32 + lane);
        uint2 h1 = __ldg(h2 + (size_t)e1.x * 32 + lane);
        uint2 hh2 = __ldg(h2 + (size_t)e2.x * 32 + lane);
        uint2 h3 = __ldg(h2 + (size_t)e3.x * 32 + lane);

        __half2 v0 = *(__half2*)&e0.y;
        __half2 v1 = *(__half2*)&e1.y;
        __half2 v2 = *(__half2*)&e2.y;
        __half2 v3 = *(__half2*)&e3.y;

        __half2 a01 = __hmul2(v0, *(__half2*)&h0.x);
        __half2 a23 = __hmul2(v0, *(__half2*)&h0.y);
        a01 = __hfma2(v1, *(__half2*)&h1.x, a01);
        a23 = __hfma2(v1, *(__half2*)&h1.y, a23);
        a01 = __hfma2(v2, *(__half2*)&hh2.x, a01);
        a23 = __hfma2(v2, *(__half2*)&hh2.y, a23);
        a01 = __hfma2(v3, *(__half2*)&h3.x, a01);
        a23 = __hfma2(v3, *(__half2*)&h3.y, a23);

        float2 f01 = __half22float2(a01);     // 4 F2F per 4 edges
        float2 f23 = __half22float2(a23);
        acc.x += f01.x; acc.y += f01.y;
        acc.z += f23.x; acc.w += f23.y;
    }
    if (i < end) {
        __half2 a01 = __float2half2_rn(0.f);
        __half2 a23 = __float2half2_rn(0.f);
        for (; i < end; i++) {
            uint2 e0 = __ldg(&g_edges[i]);
            uint2 h0 = __ldg(h2 + (size_t)e0.x * 32 + lane);
            __half2 v0 = *(__half2*)&e0.y;
            a01 = __hfma2(v0, *(__half2*)&h0.x, a01);
            a23 = __hfma2(v0, *(__half2*)&h0.y, a23);
        }
        float2 f01 = __half22float2(a01);
        float2 f23 = __half22float2(a23);
        acc.x += f01.x; acc.y += f01.y;
        acc.z += f23.x; acc.w += f23.y;
    }

    out[(size_t)r * 32 + lane] = acc;
}

// ---------------------------------------------------------------------------
// Launch: fork/join two-branch graph; aggregate joins.
// ---------------------------------------------------------------------------
extern "C" void kernel_launch(void* const* d_in, const int* in_sizes, int n_in,
                              void* d_out, int out_size)
{
    const float* x    = (const float*)d_in[0];
    const float* W    = (const float*)d_in[1];
    const float* b    = (const float*)d_in[2];
    const float* vals = (const float*)d_in[3];
    const int*   rows = (const int*)d_in[4];
    const int*   cols = (const int*)d_in[5];
    float4*      out  = (float4*)d_out;

    const int n_nodes = in_sizes[0] / DIM;
    const int n_edges = in_sizes[3];

    static cudaStream_t sB;
    static cudaEvent_t  evFork, evJoin;
    static bool init = false;
    if (!init) {
        cudaFuncSetAttribute(gemm_tc_kernel,
                             cudaFuncAttributeMaxDynamicSharedMemorySize, GEMM_SMEM);
        cudaStreamCreateWithFlags(&sB, cudaStreamNonBlocking);
        cudaEventCreateWithFlags(&evFork, cudaEventDisableTiming);
        cudaEventCreateWithFlags(&evJoin, cudaEventDisableTiming);
        init = true;
    }

    const int nb = (n_nodes + 1023) / 1024;

    // fork
    cudaEventRecord(evFork, 0);
    cudaStreamWaitEvent(sB, evFork, 0);

    // branch B: CSR build
    zero_hist_kernel<<<(n_nodes + 255) / 256, 256, 0, sB>>>(n_nodes);
    hist_kernel<<<(n_edges + 255) / 256, 256, 0, sB>>>(rows, n_edges);
    scan_a_kernel<<<nb, 1024, 0, sB>>>(n_nodes);
    scan_b_kernel<<<1, 1024, 0, sB>>>(nb);
    scan_c_kernel<<<nb, 1024, 0, sB>>>(n_nodes, n_edges);
    permute_kernel<<<(n_edges + 255) / 256, 256, 0, sB>>>(vals, rows, cols, n_edges);

    // branch A: pack W (fp16) then HMMA GEMM (fp16 h out)
    pack_w_kernel<<<(DIM * DIM + 255) / 256, 256>>>(W);
    gemm_tc_kernel<<<(n_nodes + 127) / 128, 256, GEMM_SMEM>>>(x, b, n_nodes);

    // join
    cudaEventRecord(evJoin, sB);
    cudaStreamWaitEvent(0, evJoin, 0);

    // aggregate
    {
        long long total_threads = (long long)n_nodes * 32;
        int blocks = (int)((total_threads + 255) / 256);
        aggregate_kernel<<<blocks, 256>>>(out, n_nodes);
    }
}